// round 5
// baseline (speedup 1.0000x reference)
#include <cuda_runtime.h>
#include <cuda_bf16.h>
#include <cstdint>

#define NN 50000
#define EE 400000
#define TT 4
#define DIN 64
#define DD 128
#define BG 64
#define NSTEPS 8
#define R64 ((NN + 63) / 64)        // 782
#define NB1 ((NN + 255) / 256)      // 196 scan blocks

// ---------------- device scratch ----------------
__device__ float g_h [NN * DD];
__device__ float g_h1[NN * DD];
__device__ float g_t [NN * TT * DD];     // [N][512]
__device__ float g_a [NN * DD];
__device__ float g_rs[NN * DD];
__device__ float g_zs[NN * DD];
__device__ float g_in[NN * DD];
__device__ float g_hn[NN * DD];
__device__ float g_feats[BG * DD];
// CSR by dst
__device__ int g_cnt [NN];
__device__ int g_scan[NN];
__device__ int g_off [NN + 1];
__device__ int g_part [256];
__device__ int g_part2[256];
__device__ int g_eoff[EE];
__device__ int g_gsrc[EE];
// prepped bf16 hi/lo weights, B layout [col][k]
__device__ __nv_bfloat16 g_Wt_hi [TT * DD * DD];
__device__ __nv_bfloat16 g_Wt_lo [TT * DD * DD];
__device__ __nv_bfloat16 g_Bih_hi[3 * DD * DD];
__device__ __nv_bfloat16 g_Bih_lo[3 * DD * DD];
__device__ __nv_bfloat16 g_Bhh_hi[3 * DD * DD];
__device__ __nv_bfloat16 g_Bhh_lo[3 * DD * DD];

// ---------------- helpers ----------------
__device__ __forceinline__ uint32_t smem_u32(const void* p) {
    return (uint32_t)__cvta_generic_to_shared(p);
}
__device__ __forceinline__ void ldsm_x4(uint32_t* r, uint32_t addr) {
    asm volatile("ldmatrix.sync.aligned.m8n8.x4.shared.b16 {%0,%1,%2,%3}, [%4];"
                 : "=r"(r[0]), "=r"(r[1]), "=r"(r[2]), "=r"(r[3]) : "r"(addr));
}
__device__ __forceinline__ void mma16816(float* d, const uint32_t* a, const uint32_t* b) {
    asm volatile(
        "mma.sync.aligned.m16n8k16.row.col.f32.bf16.bf16.f32 "
        "{%0,%1,%2,%3}, {%4,%5,%6,%7}, {%8,%9}, {%0,%1,%2,%3};"
        : "+f"(d[0]), "+f"(d[1]), "+f"(d[2]), "+f"(d[3])
        : "r"(a[0]), "r"(a[1]), "r"(a[2]), "r"(a[3]), "r"(b[0]), "r"(b[1]));
}
__device__ __forceinline__ void cp16(uint32_t dst, const void* src) {
    asm volatile("cp.async.cg.shared.global [%0], [%1], 16;" :: "r"(dst), "l"(src));
}
#define CP_COMMIT() asm volatile("cp.async.commit_group;" ::: "memory")
#define CP_WAIT0()  asm volatile("cp.async.wait_group 0;" ::: "memory")

#define TROW 136
#define RB   (TROW * 2)            // 272B row stride
#define AT64 (64 * RB)             // 17408
#define BT64 (64 * RB)             // 17408
#define BT128 (128 * RB)           // 34816
#define SM104 (6 * AT64)           // 104448 both kernels

// fp32 -> hi/lo bf16 split, 64 rows
__device__ __forceinline__ void load_a64_split(char* hi, char* lo,
        const float* __restrict__ src, int row0, int tid) {
#pragma unroll
    for (int i = 0; i < 8; i++) {
        int f = tid + 256 * i;                  // 2048 float4
        int r = f >> 5, c4 = (f & 31) * 4;
        int gr = row0 + r;
        float4 v = make_float4(0.f, 0.f, 0.f, 0.f);
        if (gr < NN) v = *(const float4*)(src + (size_t)gr * DD + c4);
        __nv_bfloat16 h0 = __float2bfloat16(v.x), h1 = __float2bfloat16(v.y);
        __nv_bfloat16 h2 = __float2bfloat16(v.z), h3 = __float2bfloat16(v.w);
        __nv_bfloat16 l0 = __float2bfloat16(v.x - __bfloat162float(h0));
        __nv_bfloat16 l1 = __float2bfloat16(v.y - __bfloat162float(h1));
        __nv_bfloat16 l2 = __float2bfloat16(v.z - __bfloat162float(h2));
        __nv_bfloat16 l3 = __float2bfloat16(v.w - __bfloat162float(h3));
        __nv_bfloat162 hp0 = {h0, h1}, hp1 = {h2, h3};
        __nv_bfloat162 lp0 = {l0, l1}, lp1 = {l2, l3};
        uint32_t off = r * RB + c4 * 2;
        *(uint2*)(hi + off) = make_uint2(*(uint32_t*)&hp0, *(uint32_t*)&hp1);
        *(uint2*)(lo + off) = make_uint2(*(uint32_t*)&lp0, *(uint32_t*)&lp1);
    }
}
// async copy of bf16 B tile with `cols` rows (col-major [col][128k])
template<int COLS>
__device__ __forceinline__ void load_b_async(char* bh, char* bl,
        const __nv_bfloat16* __restrict__ Bh, const __nv_bfloat16* __restrict__ Bl, int tid) {
    uint32_t uh = smem_u32(bh), ul = smem_u32(bl);
#pragma unroll
    for (int i = 0; i < COLS / 16; i++) {       // COLS*16 uint4 / 256
        int f = tid + 256 * i;
        int r = f >> 4, c8 = (f & 15) * 8;
        uint32_t off = r * RB + c8 * 2;
        cp16(uh + off, Bh + r * DD + c8);
        cp16(ul + off, Bl + r * DD + c8);
    }
}

// ---------------- transform: g_t = h @ Wmsg[y]^T + bmsg  (64x128 blocks) --
__global__ __launch_bounds__(256, 2) void transform64(const float* __restrict__ bias) {
    extern __shared__ char smem[];
    char* sAH = smem;
    char* sAL = smem + AT64;
    char* sBH = smem + 2 * AT64;
    char* sBL = smem + 2 * AT64 + BT128;
    const int tid = threadIdx.x, wid = tid >> 5, lane = tid & 31;
    const int wm = wid & 1, wn = wid >> 1;      // warp tile 32 rows x 32 cols
    const int row0 = blockIdx.x * 64;
    const int tt = blockIdx.y;

    load_b_async<128>(sBH, sBL, g_Wt_hi + tt * 16384, g_Wt_lo + tt * 16384, tid);
    CP_COMMIT();
    load_a64_split(sAH, sAL, g_h, row0, tid);
    CP_WAIT0();
    __syncthreads();

    const uint32_t aoff = (uint32_t)((wm * 32 + (lane & 15)) * RB + (lane >> 4) * 16);
    const uint32_t boff = (uint32_t)((wn * 32 + ((lane >> 4) & 1) * 8 + (lane & 7)) * RB
                                     + ((lane >> 3) & 1) * 16);
    const uint32_t uAH = smem_u32(sAH), uAL = smem_u32(sAL);
    const uint32_t uBH = smem_u32(sBH), uBL = smem_u32(sBL);

    float acc[2][4][4];
#pragma unroll
    for (int mi = 0; mi < 2; mi++)
#pragma unroll
        for (int n8 = 0; n8 < 4; n8++)
#pragma unroll
            for (int j = 0; j < 4; j++) acc[mi][n8][j] = 0.f;

#pragma unroll
    for (int t = 0; t < 3; t++) {
        uint32_t ua = (t < 2) ? uAH : uAL;
        uint32_t ub = (t == 1) ? uBL : uBH;
#pragma unroll
        for (int k = 0; k < 8; k++) {
            uint32_t kb = k * 32;
            uint32_t afr[2][4], bfr[2][4];
            ldsm_x4(afr[0], ua + aoff + kb);
            ldsm_x4(afr[1], ua + aoff + kb + 16 * RB);
            ldsm_x4(bfr[0], ub + boff + kb);
            ldsm_x4(bfr[1], ub + boff + kb + 16 * RB);
#pragma unroll
            for (int mi = 0; mi < 2; mi++)
#pragma unroll
                for (int ni = 0; ni < 2; ni++) {
                    mma16816(acc[mi][ni * 2 + 0], afr[mi], &bfr[ni][0]);
                    mma16816(acc[mi][ni * 2 + 1], afr[mi], &bfr[ni][2]);
                }
        }
    }

#pragma unroll
    for (int mi = 0; mi < 2; mi++) {
        int r0 = row0 + wm * 32 + mi * 16 + (lane >> 2);
#pragma unroll
        for (int n8 = 0; n8 < 4; n8++) {
            int col = wn * 32 + n8 * 8 + (lane & 3) * 2;
            float b0 = bias[tt * 128 + col], b1 = bias[tt * 128 + col + 1];
            if (r0 < NN)
                *(float2*)(g_t + (size_t)r0 * 512 + tt * 128 + col) =
                    make_float2(acc[mi][n8][0] + b0, acc[mi][n8][1] + b1);
            if (r0 + 8 < NN)
                *(float2*)(g_t + (size_t)(r0 + 8) * 512 + tt * 128 + col) =
                    make_float2(acc[mi][n8][2] + b0, acc[mi][n8][3] + b1);
        }
    }
}

// ---------------- fused gates GEMM (64x64 blocks, grid (782, 8)) --------
// gate = y>>1 : 0 rs = a@wih_r + h@whh_r ; 1 zs ; 2 in = a@wih_n ; 3 hn = h@whh_n
// ch = y&1 selects 64-col half.
__global__ __launch_bounds__(256, 2) void gates64() {
    extern __shared__ char smem[];
    char* sAaH = smem;
    char* sAaL = smem + AT64;
    char* sAhH = smem + 2 * AT64;
    char* sAhL = smem + 3 * AT64;
    char* sBH  = smem + 4 * AT64;
    char* sBL  = smem + 5 * AT64;
    const int tid = threadIdx.x, wid = tid >> 5, lane = tid & 31;
    const int wm = wid & 1, wn = wid >> 1;      // warp tile 32 rows x 16 cols
    const int row0 = blockIdx.x * 64;
    const int gate = blockIdx.y >> 1, ch = blockIdx.y & 1;
    const int chunk = (gate < 2) ? gate : 2;
    const int bofs = chunk * 16384 + ch * 64 * 128;

    if (gate == 3) load_b_async<64>(sBH, sBL, g_Bhh_hi + bofs, g_Bhh_lo + bofs, tid);
    else           load_b_async<64>(sBH, sBL, g_Bih_hi + bofs, g_Bih_lo + bofs, tid);
    CP_COMMIT();
    if (gate != 3) load_a64_split(sAaH, sAaL, g_a, row0, tid);
    if (gate != 2) load_a64_split(sAhH, sAhL, g_h, row0, tid);
    CP_WAIT0();
    __syncthreads();

    const uint32_t aoff = (uint32_t)((wm * 32 + (lane & 15)) * RB + (lane >> 4) * 16);
    const uint32_t boff = (uint32_t)((wn * 16 + ((lane >> 4) & 1) * 8 + (lane & 7)) * RB
                                     + ((lane >> 3) & 1) * 16);
    const uint32_t uBH = smem_u32(sBH), uBL = smem_u32(sBL);

    float acc[2][2][4];
#pragma unroll
    for (int mi = 0; mi < 2; mi++)
#pragma unroll
        for (int n8 = 0; n8 < 2; n8++)
#pragma unroll
            for (int j = 0; j < 4; j++) acc[mi][n8][j] = 0.f;

    // pass 1: A = a (gates 0..2) or h (gate 3)
    {
        uint32_t uH = (gate == 3) ? smem_u32(sAhH) : smem_u32(sAaH);
        uint32_t uL = (gate == 3) ? smem_u32(sAhL) : smem_u32(sAaL);
#pragma unroll
        for (int t = 0; t < 3; t++) {
            uint32_t ua = (t < 2) ? uH : uL;
            uint32_t ub = (t == 1) ? uBL : uBH;
#pragma unroll
            for (int k = 0; k < 8; k++) {
                uint32_t kb = k * 32;
                uint32_t afr[2][4], bfr[4];
                ldsm_x4(afr[0], ua + aoff + kb);
                ldsm_x4(afr[1], ua + aoff + kb + 16 * RB);
                ldsm_x4(bfr, ub + boff + kb);
#pragma unroll
                for (int mi = 0; mi < 2; mi++) {
                    mma16816(acc[mi][0], afr[mi], &bfr[0]);
                    mma16816(acc[mi][1], afr[mi], &bfr[2]);
                }
            }
        }
    }
    // pass 2 (r,z): A = h, B = whh chunk
    if (gate < 2) {
        __syncthreads();
        load_b_async<64>(sBH, sBL, g_Bhh_hi + bofs, g_Bhh_lo + bofs, tid);
        CP_COMMIT();
        CP_WAIT0();
        __syncthreads();
        uint32_t uH = smem_u32(sAhH), uL = smem_u32(sAhL);
#pragma unroll
        for (int t = 0; t < 3; t++) {
            uint32_t ua = (t < 2) ? uH : uL;
            uint32_t ub = (t == 1) ? uBL : uBH;
#pragma unroll
            for (int k = 0; k < 8; k++) {
                uint32_t kb = k * 32;
                uint32_t afr[2][4], bfr[4];
                ldsm_x4(afr[0], ua + aoff + kb);
                ldsm_x4(afr[1], ua + aoff + kb + 16 * RB);
                ldsm_x4(bfr, ub + boff + kb);
#pragma unroll
                for (int mi = 0; mi < 2; mi++) {
                    mma16816(acc[mi][0], afr[mi], &bfr[0]);
                    mma16816(acc[mi][1], afr[mi], &bfr[2]);
                }
            }
        }
    }

    float* C = (gate == 0) ? g_rs : (gate == 1) ? g_zs : (gate == 2) ? g_in : g_hn;
#pragma unroll
    for (int mi = 0; mi < 2; mi++) {
        int r0 = row0 + wm * 32 + mi * 16 + (lane >> 2);
#pragma unroll
        for (int n8 = 0; n8 < 2; n8++) {
            int col = ch * 64 + wn * 16 + n8 * 8 + (lane & 3) * 2;
            if (r0 < NN)
                *(float2*)(C + (size_t)r0 * DD + col) =
                    make_float2(acc[mi][n8][0], acc[mi][n8][1]);
            if (r0 + 8 < NN)
                *(float2*)(C + (size_t)(r0 + 8) * DD + col) =
                    make_float2(acc[mi][n8][2], acc[mi][n8][3]);
        }
    }
}

// ---------------- weight prep ----------------
__global__ void prep_wmsg(const float* __restrict__ Wmsg) {
    int idx = blockIdx.x * blockDim.x + threadIdx.x;
    if (idx >= TT * DD * DD) return;
    int t = idx >> 14, rem = idx & 16383, e = rem >> 7, d = rem & 127;
    float w = Wmsg[t * 16384 + d * 128 + e];
    __nv_bfloat16 hi = __float2bfloat16(w);
    g_Wt_hi[idx] = hi;
    g_Wt_lo[idx] = __float2bfloat16(w - __bfloat162float(hi));
}
__global__ void prep_gates(const float* __restrict__ wih, const float* __restrict__ whh) {
    int idx = blockIdx.x * blockDim.x + threadIdx.x;
    if (idx >= 3 * DD * DD) return;
    int c = idx >> 7, k = idx & 127;
    float wi = wih[k * 384 + c];
    float wh = whh[k * 384 + c];
    __nv_bfloat16 hi = __float2bfloat16(wi);
    g_Bih_hi[idx] = hi;
    g_Bih_lo[idx] = __float2bfloat16(wi - __bfloat162float(hi));
    __nv_bfloat16 hh = __float2bfloat16(wh);
    g_Bhh_hi[idx] = hh;
    g_Bhh_lo[idx] = __float2bfloat16(wh - __bfloat162float(hh));
}

// ---------------- init ----------------
__global__ void init_kernel(const float* __restrict__ features) {
    int idx = blockIdx.x * blockDim.x + threadIdx.x;
    if (idx >= NN * DD) return;
    int n = idx >> 7, j = idx & 127;
    float v = (j < DIN) ? features[n * DIN + j] : 0.f;
    g_h1[idx] = v;
    g_h [idx] = v;
}

// ---------------- CSR build ----------------
__global__ void zero_cnt_kernel() {
    int i = blockIdx.x * blockDim.x + threadIdx.x;
    if (i < NN) g_cnt[i] = 0;
}
__global__ void count_kernel(const int* __restrict__ dst) {
    int e = blockIdx.x * blockDim.x + threadIdx.x;
    if (e >= EE) return;
    g_eoff[e] = atomicAdd(&g_cnt[dst[e]], 1);
}
__global__ void scan_a_kernel() {
    __shared__ int s[256];
    int b = blockIdx.x, t = threadIdx.x;
    int n = b * 256 + t;
    int v = (n < NN) ? g_cnt[n] : 0;
    s[t] = v;
    __syncthreads();
    for (int d = 1; d < 256; d <<= 1) {
        int x = (t >= d) ? s[t - d] : 0;
        __syncthreads();
        s[t] += x;
        __syncthreads();
    }
    if (n < NN) g_scan[n] = s[t] - v;
    if (t == 255) g_part[b] = s[255];
}
__global__ void scan_b_kernel() {
    __shared__ int s[256];
    int t = threadIdx.x;
    int v = (t < NB1) ? g_part[t] : 0;
    s[t] = v;
    __syncthreads();
    for (int d = 1; d < 256; d <<= 1) {
        int x = (t >= d) ? s[t - d] : 0;
        __syncthreads();
        s[t] += x;
        __syncthreads();
    }
    g_part2[t] = s[t] - v;
}
__global__ void scan_c_kernel() {
    int n = blockIdx.x * blockDim.x + threadIdx.x;
    if (n < NN) g_off[n] = g_scan[n] + g_part2[n >> 8];
    if (n == 0) g_off[NN] = EE;
}
__global__ void fill_kernel(const int* __restrict__ src, const int* __restrict__ dst,
                            const int* __restrict__ et) {
    int e = blockIdx.x * blockDim.x + threadIdx.x;
    if (e >= EE) return;
    int pos = g_off[dst[e]] + g_eoff[e];
    g_gsrc[pos] = src[e] * 512 + et[e] * 128;
}

// ---------------- gather ----------------
__global__ __launch_bounds__(256) void gather_kernel() {
    int w = blockIdx.x * 8 + (threadIdx.x >> 5);
    if (w >= NN) return;
    int lane = threadIdx.x & 31;
    int b0 = g_off[w], b1 = g_off[w + 1];
    float4 acc = make_float4(0.f, 0.f, 0.f, 0.f);
    for (int i = b0; i < b1; i++) {
        int so = g_gsrc[i];
        float4 v = *(const float4*)&g_t[so + lane * 4];
        acc.x += v.x; acc.y += v.y; acc.z += v.z; acc.w += v.w;
    }
    *(float4*)&g_a[w * DD + lane * 4] = acc;
}

// ---------------- GRU pointwise ----------------
__global__ void gru_kernel(const float* __restrict__ bih, const float* __restrict__ bhh) {
    int idx = blockIdx.x * blockDim.x + threadIdx.x;
    if (idx >= NN * 32) return;
    int n = idx >> 5, q = idx & 31;
    int col = q * 4;
    size_t o = (size_t)n * DD + col;
    float4 rs = *(const float4*)&g_rs[o];
    float4 zs = *(const float4*)&g_zs[o];
    float4 iv = *(const float4*)&g_in[o];
    float4 hv = *(const float4*)&g_hn[o];
    float4 h  = *(const float4*)&g_h [o];
    float4 br  = *(const float4*)&bih[col];
    float4 br2 = *(const float4*)&bhh[col];
    float4 bz  = *(const float4*)&bih[128 + col];
    float4 bz2 = *(const float4*)&bhh[128 + col];
    float4 bn  = *(const float4*)&bih[256 + col];
    float4 bn2 = *(const float4*)&bhh[256 + col];
    float4 out;
    {
        float r = 1.f / (1.f + expf(-(rs.x + br.x + br2.x)));
        float z = 1.f / (1.f + expf(-(zs.x + bz.x + bz2.x)));
        float ng = tanhf(iv.x + bn.x + r * (hv.x + bn2.x));
        out.x = (1.f - z) * ng + z * h.x;
    }
    {
        float r = 1.f / (1.f + expf(-(rs.y + br.y + br2.y)));
        float z = 1.f / (1.f + expf(-(zs.y + bz.y + bz2.y)));
        float ng = tanhf(iv.y + bn.y + r * (hv.y + bn2.y));
        out.y = (1.f - z) * ng + z * h.y;
    }
    {
        float r = 1.f / (1.f + expf(-(rs.z + br.z + br2.z)));
        float z = 1.f / (1.f + expf(-(zs.z + bz.z + bz2.z)));
        float ng = tanhf(iv.z + bn.z + r * (hv.z + bn2.z));
        out.z = (1.f - z) * ng + z * h.z;
    }
    {
        float r = 1.f / (1.f + expf(-(rs.w + br.w + br2.w)));
        float z = 1.f / (1.f + expf(-(zs.w + bz.w + bz2.w)));
        float ng = tanhf(iv.w + bn.w + r * (hv.w + bn2.w));
        out.w = (1.f - z) * ng + z * h.w;
    }
    *(float4*)&g_h[o] = out;
}

// ---------------- pooling + classifier ----------------
__global__ void zero_feats_kernel() {
    int i = blockIdx.x * blockDim.x + threadIdx.x;
    if (i < BG * DD) g_feats[i] = 0.f;
}
__global__ void pool_kernel(const int* __restrict__ n2g) {
    int n0 = blockIdx.x * 64;
    int j  = threadIdx.x;
    if (n0 >= NN) return;
    float acc = 0.f;
    int cur = n2g[n0];
    for (int i = 0; i < 64; i++) {
        int n = n0 + i;
        if (n >= NN) break;
        int g = n2g[n];
        if (g != cur) {
            atomicAdd(&g_feats[cur * DD + j], acc);
            acc = 0.f; cur = g;
        }
        acc += g_h[n * DD + j] + g_h1[n * DD + j];
    }
    atomicAdd(&g_feats[cur * DD + j], acc);
}
__global__ void cls_kernel(const float* __restrict__ Wc,
                           const float* __restrict__ bc,
                           float* __restrict__ out) {
    int tid = threadIdx.x;
    if (tid >= BG * 2) return;
    int g = tid >> 1, c = tid & 1;
    float s = bc[c];
#pragma unroll 8
    for (int k = 0; k < DD; k++) s += g_feats[g * DD + k] * Wc[k * 2 + c];
    out[g * 2 + c] = s;
}

// ---------------- launch ----------------
extern "C" void kernel_launch(void* const* d_in, const int* in_sizes, int n_in,
                              void* d_out, int out_size) {
    const float* features = (const float*)d_in[0];
    const int*   src      = (const int*)  d_in[1];
    const int*   dst      = (const int*)  d_in[2];
    const int*   etype    = (const int*)  d_in[3];
    const int*   n2g      = (const int*)  d_in[4];
    const float* W_msg    = (const float*)d_in[5];
    const float* b_msg    = (const float*)d_in[6];
    const float* w_ih     = (const float*)d_in[7];
    const float* b_ih     = (const float*)d_in[8];
    const float* w_hh     = (const float*)d_in[9];
    const float* b_hh     = (const float*)d_in[10];
    const float* W_cls    = (const float*)d_in[11];
    const float* b_cls    = (const float*)d_in[12];
    float* out = (float*)d_out;

    static int smem_set = 0;
    if (!smem_set) {
        cudaFuncSetAttribute(transform64,
                             cudaFuncAttributeMaxDynamicSharedMemorySize, SM104);
        cudaFuncSetAttribute(gates64,
                             cudaFuncAttributeMaxDynamicSharedMemorySize, SM104);
        smem_set = 1;
    }

    // prologue
    prep_wmsg<<<(TT * DD * DD + 255) / 256, 256>>>(W_msg);
    prep_gates<<<(3 * DD * DD + 255) / 256, 256>>>(w_ih, w_hh);
    init_kernel<<<(NN * DD + 255) / 256, 256>>>(features);
    zero_cnt_kernel<<<(NN + 255) / 256, 256>>>();
    count_kernel<<<(EE + 255) / 256, 256>>>(dst);
    scan_a_kernel<<<NB1, 256>>>();
    scan_b_kernel<<<1, 256>>>();
    scan_c_kernel<<<(NN + 255) / 256, 256>>>();
    fill_kernel<<<(EE + 255) / 256, 256>>>(src, dst, etype);

    for (int s = 0; s < NSTEPS; s++) {
        transform64<<<dim3(R64, TT), 256, SM104>>>(b_msg);
        gather_kernel<<<(NN + 7) / 8, 256>>>();
        gates64<<<dim3(R64, 8), 256, SM104>>>();
        gru_kernel<<<(NN * 32 + 255) / 256, 256>>>(b_ih, b_hh);
    }

    zero_feats_kernel<<<(BG * DD + 255) / 256, 256>>>();
    pool_kernel<<<(NN + 63) / 64, 128>>>(n2g);
    cls_kernel<<<1, 128>>>(W_cls, b_cls, out);
}

// round 6
// speedup vs baseline: 1.0038x; 1.0038x over previous
#include <cuda_runtime.h>
#include <cuda_bf16.h>
#include <cstdint>

#define NN 50000
#define EE 400000
#define TT 4
#define DIN 64
#define DD 128
#define BG 64
#define NSTEPS 8
#define RTILES ((NN + 127) / 128)   // 391
#define NB1 ((NN + 255) / 256)      // 196

// ---------------- device scratch ----------------
__device__ float g_h [NN * DD];
__device__ float g_h1[NN * DD];
__device__ float g_t [NN * TT * DD];
__device__ float g_a [NN * DD];
__device__ float g_rs[NN * DD];
__device__ float g_zs[NN * DD];
__device__ float g_in[NN * DD];
__device__ float g_hn[NN * DD];
__device__ float g_feats[BG * DD];
// CSR by dst
__device__ int g_cnt [NN];
__device__ int g_scan[NN];
__device__ int g_off [NN + 1];
__device__ int g_part [256];
__device__ int g_part2[256];
__device__ int g_eoff[EE];
__device__ int g_gsrc[EE];
// B matrices pre-packed in mma.m16n8k16 B-fragment order:
// index = mat*4096 + (ks*16 + cb)*32 + lane ; uint2 = {B[k0..k0+1][c], B[k0+8..k0+9][c]}
// with c = cb*8 + lane/4, k0 = ks*16 + (lane%4)*2
__device__ uint2 g_pWt_hi[TT * 4096];
__device__ uint2 g_pWt_lo[TT * 4096];
__device__ uint2 g_pIh_hi[3 * 4096];
__device__ uint2 g_pIh_lo[3 * 4096];
__device__ uint2 g_pHh_hi[3 * 4096];
__device__ uint2 g_pHh_lo[3 * 4096];

// ---------------- helpers ----------------
__device__ __forceinline__ uint32_t smem_u32(const void* p) {
    return (uint32_t)__cvta_generic_to_shared(p);
}
__device__ __forceinline__ void ldsm_x4(uint32_t* r, uint32_t addr) {
    asm volatile("ldmatrix.sync.aligned.m8n8.x4.shared.b16 {%0,%1,%2,%3}, [%4];"
                 : "=r"(r[0]), "=r"(r[1]), "=r"(r[2]), "=r"(r[3]) : "r"(addr));
}
__device__ __forceinline__ void mma16816(float* d, const uint32_t* a, const uint32_t* b) {
    asm volatile(
        "mma.sync.aligned.m16n8k16.row.col.f32.bf16.bf16.f32 "
        "{%0,%1,%2,%3}, {%4,%5,%6,%7}, {%8,%9}, {%0,%1,%2,%3};"
        : "+f"(d[0]), "+f"(d[1]), "+f"(d[2]), "+f"(d[3])
        : "r"(a[0]), "r"(a[1]), "r"(a[2]), "r"(a[3]), "r"(b[0]), "r"(b[1]));
}

#define TROW 136
#define RB   (TROW * 2)            // 272
#define AT128 (128 * RB)           // 34816
#define SM2A  (2 * AT128)          // 69632

// fp32 -> hi/lo bf16 split (128 rows)
__device__ __forceinline__ void load_a_split(char* hi, char* lo,
        const float* __restrict__ src, int row0, int tid) {
#pragma unroll
    for (int i = 0; i < 16; i++) {
        int f = tid + 256 * i;
        int r = f >> 5, c4 = (f & 31) * 4;
        int gr = row0 + r;
        float4 v = make_float4(0.f, 0.f, 0.f, 0.f);
        if (gr < NN) v = *(const float4*)(src + (size_t)gr * DD + c4);
        __nv_bfloat16 h0 = __float2bfloat16(v.x), h1 = __float2bfloat16(v.y);
        __nv_bfloat16 h2 = __float2bfloat16(v.z), h3 = __float2bfloat16(v.w);
        __nv_bfloat16 l0 = __float2bfloat16(v.x - __bfloat162float(h0));
        __nv_bfloat16 l1 = __float2bfloat16(v.y - __bfloat162float(h1));
        __nv_bfloat16 l2 = __float2bfloat16(v.z - __bfloat162float(h2));
        __nv_bfloat16 l3 = __float2bfloat16(v.w - __bfloat162float(h3));
        __nv_bfloat162 hp0 = {h0, h1}, hp1 = {h2, h3};
        __nv_bfloat162 lp0 = {l0, l1}, lp1 = {l2, l3};
        uint32_t off = r * RB + c4 * 2;
        *(uint2*)(hi + off) = make_uint2(*(uint32_t*)&hp0, *(uint32_t*)&hp1);
        *(uint2*)(lo + off) = make_uint2(*(uint32_t*)&lp0, *(uint32_t*)&lp1);
    }
}

// 3-term split 128x128xK=128 product into acc (B from packed global fragments)
__device__ __forceinline__ void product3(float acc[2][8][4],
        uint32_t uAH, uint32_t uAL, uint32_t aoff,
        const uint2* __restrict__ pBh, const uint2* __restrict__ pBl,
        int wn, int lane) {
    const uint2* bh = pBh + wn * 256 + lane;
    const uint2* bl = pBl + wn * 256 + lane;
    // pass 1: B = hi; A = hi and lo
#pragma unroll
    for (int ks = 0; ks < 8; ks++) {
        uint32_t kb = ks * 32;
        uint32_t ah[2][4], al[2][4];
        ldsm_x4(ah[0], uAH + aoff + kb);
        ldsm_x4(ah[1], uAH + aoff + kb + 16 * RB);
        ldsm_x4(al[0], uAL + aoff + kb);
        ldsm_x4(al[1], uAL + aoff + kb + 16 * RB);
#pragma unroll
        for (int n8 = 0; n8 < 8; n8++) {
            uint2 b = bh[(ks * 16 + n8) * 32];
            mma16816(acc[0][n8], ah[0], (const uint32_t*)&b);
            mma16816(acc[1][n8], ah[1], (const uint32_t*)&b);
            mma16816(acc[0][n8], al[0], (const uint32_t*)&b);
            mma16816(acc[1][n8], al[1], (const uint32_t*)&b);
        }
    }
    // pass 2: B = lo; A = hi
#pragma unroll
    for (int ks = 0; ks < 8; ks++) {
        uint32_t kb = ks * 32;
        uint32_t ah[2][4];
        ldsm_x4(ah[0], uAH + aoff + kb);
        ldsm_x4(ah[1], uAH + aoff + kb + 16 * RB);
#pragma unroll
        for (int n8 = 0; n8 < 8; n8++) {
            uint2 b = bl[(ks * 16 + n8) * 32];
            mma16816(acc[0][n8], ah[0], (const uint32_t*)&b);
            mma16816(acc[1][n8], ah[1], (const uint32_t*)&b);
        }
    }
}

// ---------------- transform: g_t[:, tt*128:+128] = h @ Wmsg[tt]^T + bmsg --
// grid (391, 2): y handles types {2y, 2y+1}; A (=h) loaded once per block.
__global__ __launch_bounds__(256, 2) void transform_pk(const float* __restrict__ bias) {
    extern __shared__ char smem[];
    char* sAH = smem;
    char* sAL = smem + AT128;
    const int tid = threadIdx.x, wid = tid >> 5, lane = tid & 31;
    const int wm = wid & 3, wn = wid >> 2;
    const int row0 = blockIdx.x * 128;

    load_a_split(sAH, sAL, g_h, row0, tid);
    __syncthreads();

    const uint32_t aoff = (uint32_t)((wm * 32 + (lane & 15)) * RB + (lane >> 4) * 16);
    const uint32_t uAH = smem_u32(sAH), uAL = smem_u32(sAL);

#pragma unroll 1
    for (int i = 0; i < 2; i++) {
        int tt = blockIdx.y * 2 + i;
        float acc[2][8][4];
#pragma unroll
        for (int mi = 0; mi < 2; mi++)
#pragma unroll
            for (int n8 = 0; n8 < 8; n8++)
#pragma unroll
                for (int j = 0; j < 4; j++) acc[mi][n8][j] = 0.f;
        product3(acc, uAH, uAL, aoff, g_pWt_hi + tt * 4096, g_pWt_lo + tt * 4096,
                 wn, lane);
#pragma unroll
        for (int mi = 0; mi < 2; mi++) {
            int r0 = row0 + wm * 32 + mi * 16 + (lane >> 2);
#pragma unroll
            for (int n8 = 0; n8 < 8; n8++) {
                int col = wn * 64 + n8 * 8 + (lane & 3) * 2;
                float b0 = bias[tt * 128 + col], b1 = bias[tt * 128 + col + 1];
                if (r0 < NN)
                    *(float2*)(g_t + (size_t)r0 * 512 + tt * 128 + col) =
                        make_float2(acc[mi][n8][0] + b0, acc[mi][n8][1] + b1);
                if (r0 + 8 < NN)
                    *(float2*)(g_t + (size_t)(r0 + 8) * 512 + tt * 128 + col) =
                        make_float2(acc[mi][n8][2] + b0, acc[mi][n8][3] + b1);
            }
        }
    }
}

// ---------------- gi3: {rs,zs,in}[chunk y] = a @ wih_chunk^T  ------------
__global__ __launch_bounds__(256, 2) void gi3_kernel() {
    extern __shared__ char smem[];
    char* sAH = smem;
    char* sAL = smem + AT128;
    const int tid = threadIdx.x, wid = tid >> 5, lane = tid & 31;
    const int wm = wid & 3, wn = wid >> 2;
    const int row0 = blockIdx.x * 128;
    const int ck = blockIdx.y;

    load_a_split(sAH, sAL, g_a, row0, tid);
    __syncthreads();

    const uint32_t aoff = (uint32_t)((wm * 32 + (lane & 15)) * RB + (lane >> 4) * 16);
    float acc[2][8][4];
#pragma unroll
    for (int mi = 0; mi < 2; mi++)
#pragma unroll
        for (int n8 = 0; n8 < 8; n8++)
#pragma unroll
            for (int j = 0; j < 4; j++) acc[mi][n8][j] = 0.f;
    product3(acc, smem_u32(sAH), smem_u32(sAL), aoff,
             g_pIh_hi + ck * 4096, g_pIh_lo + ck * 4096, wn, lane);

    float* C = (ck == 0) ? g_rs : (ck == 1) ? g_zs : g_in;
#pragma unroll
    for (int mi = 0; mi < 2; mi++) {
        int r0 = row0 + wm * 32 + mi * 16 + (lane >> 2);
#pragma unroll
        for (int n8 = 0; n8 < 8; n8++) {
            int col = wn * 64 + n8 * 8 + (lane & 3) * 2;
            if (r0 < NN)
                *(float2*)(C + (size_t)r0 * DD + col) =
                    make_float2(acc[mi][n8][0], acc[mi][n8][1]);
            if (r0 + 8 < NN)
                *(float2*)(C + (size_t)(r0 + 8) * DD + col) =
                    make_float2(acc[mi][n8][2], acc[mi][n8][3]);
        }
    }
}

// ---------------- gh3: h @ whh_chunk^T ; y<2 adds into rs/zs, y=2 -> hn --
__global__ __launch_bounds__(256, 2) void gh3_kernel() {
    extern __shared__ char smem[];
    char* sAH = smem;
    char* sAL = smem + AT128;
    const int tid = threadIdx.x, wid = tid >> 5, lane = tid & 31;
    const int wm = wid & 3, wn = wid >> 2;
    const int row0 = blockIdx.x * 128;
    const int ck = blockIdx.y;

    load_a_split(sAH, sAL, g_h, row0, tid);
    __syncthreads();

    const uint32_t aoff = (uint32_t)((wm * 32 + (lane & 15)) * RB + (lane >> 4) * 16);
    float acc[2][8][4];
#pragma unroll
    for (int mi = 0; mi < 2; mi++)
#pragma unroll
        for (int n8 = 0; n8 < 8; n8++)
#pragma unroll
            for (int j = 0; j < 4; j++) acc[mi][n8][j] = 0.f;
    product3(acc, smem_u32(sAH), smem_u32(sAL), aoff,
             g_pHh_hi + ck * 4096, g_pHh_lo + ck * 4096, wn, lane);

    if (ck < 2) {
        float* C = (ck == 0) ? g_rs : g_zs;
#pragma unroll
        for (int mi = 0; mi < 2; mi++) {
            int r0 = row0 + wm * 32 + mi * 16 + (lane >> 2);
#pragma unroll
            for (int n8 = 0; n8 < 8; n8++) {
                int col = wn * 64 + n8 * 8 + (lane & 3) * 2;
                if (r0 < NN) {
                    float2 o = *(float2*)(C + (size_t)r0 * DD + col);
                    *(float2*)(C + (size_t)r0 * DD + col) =
                        make_float2(o.x + acc[mi][n8][0], o.y + acc[mi][n8][1]);
                }
                if (r0 + 8 < NN) {
                    float2 o = *(float2*)(C + (size_t)(r0 + 8) * DD + col);
                    *(float2*)(C + (size_t)(r0 + 8) * DD + col) =
                        make_float2(o.x + acc[mi][n8][2], o.y + acc[mi][n8][3]);
                }
            }
        }
    } else {
#pragma unroll
        for (int mi = 0; mi < 2; mi++) {
            int r0 = row0 + wm * 32 + mi * 16 + (lane >> 2);
#pragma unroll
            for (int n8 = 0; n8 < 8; n8++) {
                int col = wn * 64 + n8 * 8 + (lane & 3) * 2;
                if (r0 < NN)
                    *(float2*)(g_hn + (size_t)r0 * DD + col) =
                        make_float2(acc[mi][n8][0], acc[mi][n8][1]);
                if (r0 + 8 < NN)
                    *(float2*)(g_hn + (size_t)(r0 + 8) * DD + col) =
                        make_float2(acc[mi][n8][2], acc[mi][n8][3]);
            }
        }
    }
}

// ---------------- weight prep (packed B fragments) ----------------
// B[c][k] = W[k][c]; uint2 = { (B[k0][c],B[k0+1][c]) , (B[k0+8][c],B[k0+9][c]) }
__device__ __forceinline__ uint2 pack_frag(float w0, float w1, float w8, float w9, bool lo) {
    __nv_bfloat16 a0 = __float2bfloat16(w0), a1 = __float2bfloat16(w1);
    __nv_bfloat16 a8 = __float2bfloat16(w8), a9 = __float2bfloat16(w9);
    if (lo) {
        a0 = __float2bfloat16(w0 - __bfloat162float(a0));
        a1 = __float2bfloat16(w1 - __bfloat162float(a1));
        a8 = __float2bfloat16(w8 - __bfloat162float(a8));
        a9 = __float2bfloat16(w9 - __bfloat162float(a9));
    }
    __nv_bfloat162 p0 = {a0, a1}, p1 = {a8, a9};
    return make_uint2(*(uint32_t*)&p0, *(uint32_t*)&p1);
}
__global__ void prep_wmsg_pk(const float* __restrict__ Wmsg) {
    int idx = blockIdx.x * blockDim.x + threadIdx.x;
    if (idx >= TT * 4096) return;
    int t = idx >> 12, r = idx & 4095;
    int ks = r >> 9, cb = (r >> 5) & 15, lane = r & 31;
    int c = cb * 8 + (lane >> 2), k0 = ks * 16 + (lane & 3) * 2;
    const float* W = Wmsg + t * 16384;
    float w0 = W[k0 * 128 + c],       w1 = W[(k0 + 1) * 128 + c];
    float w8 = W[(k0 + 8) * 128 + c], w9 = W[(k0 + 9) * 128 + c];
    g_pWt_hi[idx] = pack_frag(w0, w1, w8, w9, false);
    g_pWt_lo[idx] = pack_frag(w0, w1, w8, w9, true);
}
__global__ void prep_gates_pk(const float* __restrict__ wih, const float* __restrict__ whh) {
    int idx = blockIdx.x * blockDim.x + threadIdx.x;
    if (idx >= 3 * 4096) return;
    int ck = idx >> 12, r = idx & 4095;
    int ks = r >> 9, cb = (r >> 5) & 15, lane = r & 31;
    int c = ck * 128 + cb * 8 + (lane >> 2), k0 = ks * 16 + (lane & 3) * 2;
    float i0 = wih[k0 * 384 + c],       i1 = wih[(k0 + 1) * 384 + c];
    float i8 = wih[(k0 + 8) * 384 + c], i9 = wih[(k0 + 9) * 384 + c];
    g_pIh_hi[idx] = pack_frag(i0, i1, i8, i9, false);
    g_pIh_lo[idx] = pack_frag(i0, i1, i8, i9, true);
    float h0 = whh[k0 * 384 + c],       h1 = whh[(k0 + 1) * 384 + c];
    float h8 = whh[(k0 + 8) * 384 + c], h9 = whh[(k0 + 9) * 384 + c];
    g_pHh_hi[idx] = pack_frag(h0, h1, h8, h9, false);
    g_pHh_lo[idx] = pack_frag(h0, h1, h8, h9, true);
}

// ---------------- init ----------------
__global__ void init_kernel(const float* __restrict__ features) {
    int idx = blockIdx.x * blockDim.x + threadIdx.x;
    if (idx >= NN * DD) return;
    int n = idx >> 7, j = idx & 127;
    float v = (j < DIN) ? features[n * DIN + j] : 0.f;
    g_h1[idx] = v;
    g_h [idx] = v;
}

// ---------------- CSR build ----------------
__global__ void zero_cnt_kernel() {
    int i = blockIdx.x * blockDim.x + threadIdx.x;
    if (i < NN) g_cnt[i] = 0;
}
__global__ void count_kernel(const int* __restrict__ dst) {
    int e = blockIdx.x * blockDim.x + threadIdx.x;
    if (e >= EE) return;
    g_eoff[e] = atomicAdd(&g_cnt[dst[e]], 1);
}
__global__ void scan_a_kernel() {
    __shared__ int s[256];
    int b = blockIdx.x, t = threadIdx.x;
    int n = b * 256 + t;
    int v = (n < NN) ? g_cnt[n] : 0;
    s[t] = v;
    __syncthreads();
    for (int d = 1; d < 256; d <<= 1) {
        int x = (t >= d) ? s[t - d] : 0;
        __syncthreads();
        s[t] += x;
        __syncthreads();
    }
    if (n < NN) g_scan[n] = s[t] - v;
    if (t == 255) g_part[b] = s[255];
}
__global__ void scan_b_kernel() {
    __shared__ int s[256];
    int t = threadIdx.x;
    int v = (t < NB1) ? g_part[t] : 0;
    s[t] = v;
    __syncthreads();
    for (int d = 1; d < 256; d <<= 1) {
        int x = (t >= d) ? s[t - d] : 0;
        __syncthreads();
        s[t] += x;
        __syncthreads();
    }
    g_part2[t] = s[t] - v;
}
__global__ void scan_c_kernel() {
    int n = blockIdx.x * blockDim.x + threadIdx.x;
    if (n < NN) g_off[n] = g_scan[n] + g_part2[n >> 8];
    if (n == 0) g_off[NN] = EE;
}
__global__ void fill_kernel(const int* __restrict__ src, const int* __restrict__ dst,
                            const int* __restrict__ et) {
    int e = blockIdx.x * blockDim.x + threadIdx.x;
    if (e >= EE) return;
    int pos = g_off[dst[e]] + g_eoff[e];
    g_gsrc[pos] = src[e] * 512 + et[e] * 128;
}

// ---------------- gather ----------------
__global__ __launch_bounds__(256) void gather_kernel() {
    int w = blockIdx.x * 8 + (threadIdx.x >> 5);
    if (w >= NN) return;
    int lane = threadIdx.x & 31;
    int b0 = g_off[w], b1 = g_off[w + 1];
    float4 acc = make_float4(0.f, 0.f, 0.f, 0.f);
    for (int i = b0; i < b1; i++) {
        int so = g_gsrc[i];
        float4 v = *(const float4*)&g_t[so + lane * 4];
        acc.x += v.x; acc.y += v.y; acc.z += v.z; acc.w += v.w;
    }
    *(float4*)&g_a[w * DD + lane * 4] = acc;
}

// ---------------- GRU pointwise ----------------
__global__ void gru_kernel(const float* __restrict__ bih, const float* __restrict__ bhh) {
    int idx = blockIdx.x * blockDim.x + threadIdx.x;
    if (idx >= NN * 32) return;
    int n = idx >> 5, q = idx & 31;
    int col = q * 4;
    size_t o = (size_t)n * DD + col;
    float4 rs = *(const float4*)&g_rs[o];
    float4 zs = *(const float4*)&g_zs[o];
    float4 iv = *(const float4*)&g_in[o];
    float4 hv = *(const float4*)&g_hn[o];
    float4 h  = *(const float4*)&g_h [o];
    float4 br  = *(const float4*)&bih[col];
    float4 br2 = *(const float4*)&bhh[col];
    float4 bz  = *(const float4*)&bih[128 + col];
    float4 bz2 = *(const float4*)&bhh[128 + col];
    float4 bn  = *(const float4*)&bih[256 + col];
    float4 bn2 = *(const float4*)&bhh[256 + col];
    float4 out;
    {
        float r = 1.f / (1.f + expf(-(rs.x + br.x + br2.x)));
        float z = 1.f / (1.f + expf(-(zs.x + bz.x + bz2.x)));
        float ng = tanhf(iv.x + bn.x + r * (hv.x + bn2.x));
        out.x = (1.f - z) * ng + z * h.x;
    }
    {
        float r = 1.f / (1.f + expf(-(rs.y + br.y + br2.y)));
        float z = 1.f / (1.f + expf(-(zs.y + bz.y + bz2.y)));
        float ng = tanhf(iv.y + bn.y + r * (hv.y + bn2.y));
        out.y = (1.f - z) * ng + z * h.y;
    }
    {
        float r = 1.f / (1.f + expf(-(rs.z + br.z + br2.z)));
        float z = 1.f / (1.f + expf(-(zs.z + bz.z + bz2.z)));
        float ng = tanhf(iv.z + bn.z + r * (hv.z + bn2.z));
        out.z = (1.f - z) * ng + z * h.z;
    }
    {
        float r = 1.f / (1.f + expf(-(rs.w + br.w + br2.w)));
        float z = 1.f / (1.f + expf(-(zs.w + bz.w + bz2.w)));
        float ng = tanhf(iv.w + bn.w + r * (hv.w + bn2.w));
        out.w = (1.f - z) * ng + z * h.w;
    }
    *(float4*)&g_h[o] = out;
}

// ---------------- pooling + classifier ----------------
__global__ void zero_feats_kernel() {
    int i = blockIdx.x * blockDim.x + threadIdx.x;
    if (i < BG * DD) g_feats[i] = 0.f;
}
__global__ void pool_kernel(const int* __restrict__ n2g) {
    int n0 = blockIdx.x * 64;
    int j  = threadIdx.x;
    if (n0 >= NN) return;
    float acc = 0.f;
    int cur = n2g[n0];
    for (int i = 0; i < 64; i++) {
        int n = n0 + i;
        if (n >= NN) break;
        int g = n2g[n];
        if (g != cur) {
            atomicAdd(&g_feats[cur * DD + j], acc);
            acc = 0.f; cur = g;
        }
        acc += g_h[n * DD + j] + g_h1[n * DD + j];
    }
    atomicAdd(&g_feats[cur * DD + j], acc);
}
__global__ void cls_kernel(const float* __restrict__ Wc,
                           const float* __restrict__ bc,
                           float* __restrict__ out) {
    int tid = threadIdx.x;
    if (tid >= BG * 2) return;
    int g = tid >> 1, c = tid & 1;
    float s = bc[c];
#pragma unroll 8
    for (int k = 0; k < DD; k++) s += g_feats[g * DD + k] * Wc[k * 2 + c];
    out[g * 2 + c] = s;
}

// ---------------- launch ----------------
extern "C" void kernel_launch(void* const* d_in, const int* in_sizes, int n_in,
                              void* d_out, int out_size) {
    const float* features = (const float*)d_in[0];
    const int*   src      = (const int*)  d_in[1];
    const int*   dst      = (const int*)  d_in[2];
    const int*   etype    = (const int*)  d_in[3];
    const int*   n2g      = (const int*)  d_in[4];
    const float* W_msg    = (const float*)d_in[5];
    const float* b_msg    = (const float*)d_in[6];
    const float* w_ih     = (const float*)d_in[7];
    const float* b_ih     = (const float*)d_in[8];
    const float* w_hh     = (const float*)d_in[9];
    const float* b_hh     = (const float*)d_in[10];
    const float* W_cls    = (const float*)d_in[11];
    const float* b_cls    = (const float*)d_in[12];
    float* out = (float*)d_out;

    static int smem_set = 0;
    if (!smem_set) {
        cudaFuncSetAttribute(transform_pk,
                             cudaFuncAttributeMaxDynamicSharedMemorySize, SM2A);
        cudaFuncSetAttribute(gi3_kernel,
                             cudaFuncAttributeMaxDynamicSharedMemorySize, SM2A);
        cudaFuncSetAttribute(gh3_kernel,
                             cudaFuncAttributeMaxDynamicSharedMemorySize, SM2A);
        smem_set = 1;
    }

    // prologue
    prep_wmsg_pk<<<(TT * 4096 + 255) / 256, 256>>>(W_msg);
    prep_gates_pk<<<(3 * 4096 + 255) / 256, 256>>>(w_ih, w_hh);
    init_kernel<<<(NN * DD + 255) / 256, 256>>>(features);
    zero_cnt_kernel<<<(NN + 255) / 256, 256>>>();
    count_kernel<<<(EE + 255) / 256, 256>>>(dst);
    scan_a_kernel<<<NB1, 256>>>();
    scan_b_kernel<<<1, 256>>>();
    scan_c_kernel<<<(NN + 255) / 256, 256>>>();
    fill_kernel<<<(EE + 255) / 256, 256>>>(src, dst, etype);

    for (int s = 0; s < NSTEPS; s++) {
        transform_pk<<<dim3(RTILES, 2), 256, SM2A>>>(b_msg);
        gather_kernel<<<(NN + 7) / 8, 256>>>();
        gi3_kernel<<<dim3(RTILES, 3), 256, SM2A>>>();
        gh3_kernel<<<dim3(RTILES, 3), 256, SM2A>>>();
        gru_kernel<<<(NN * 32 + 255) / 256, 256>>>(b_ih, b_hh);
    }

    zero_feats_kernel<<<(BG * DD + 255) / 256, 256>>>();
    pool_kernel<<<(NN + 63) / 64, 128>>>(n2g);
    cls_kernel<<<1, 128>>>(W_cls, b_cls, out);
}

// round 7
// speedup vs baseline: 1.0273x; 1.0234x over previous
#include <cuda_runtime.h>
#include <cuda_bf16.h>
#include <cstdint>

#define NN 50000
#define EE 400000
#define TT 4
#define DIN 64
#define DD 128
#define BG 64
#define NSTEPS 8
#define RTILES ((NN + 127) / 128)   // 391
#define NB1 ((NN + 255) / 256)      // 196

// ---------------- device scratch ----------------
__device__ float g_h [NN * DD];
__device__ float g_h1[NN * DD];
__device__ float g_t [NN * TT * DD];
__device__ float g_a [NN * DD];
__device__ float g_rs[NN * DD];
__device__ float g_zs[NN * DD];
__device__ float g_in[NN * DD];
__device__ float g_hn[NN * DD];
__device__ float g_feats[BG * DD];
// CSR by dst
__device__ int g_cnt [NN];
__device__ int g_scan[NN];
__device__ int g_off [NN + 1];
__device__ int g_part [256];
__device__ int g_part2[256];
__device__ int g_eoff[EE];
__device__ int g_gsrc[EE];
// prepped bf16 hi/lo weights, B layout [col][k] (k contiguous)
__device__ __nv_bfloat16 g_Wt_hi [TT * DD * DD];
__device__ __nv_bfloat16 g_Wt_lo [TT * DD * DD];
__device__ __nv_bfloat16 g_Bih_hi[3 * DD * DD];
__device__ __nv_bfloat16 g_Bih_lo[3 * DD * DD];
__device__ __nv_bfloat16 g_Bhh_hi[3 * DD * DD];
__device__ __nv_bfloat16 g_Bhh_lo[3 * DD * DD];

// ---------------- helpers ----------------
__device__ __forceinline__ uint32_t smem_u32(const void* p) {
    return (uint32_t)__cvta_generic_to_shared(p);
}
__device__ __forceinline__ void ldsm_x4(uint32_t* r, uint32_t addr) {
    asm volatile("ldmatrix.sync.aligned.m8n8.x4.shared.b16 {%0,%1,%2,%3}, [%4];"
                 : "=r"(r[0]), "=r"(r[1]), "=r"(r[2]), "=r"(r[3]) : "r"(addr));
}
__device__ __forceinline__ void mma16816(float* d, const uint32_t* a, const uint32_t* b) {
    asm volatile(
        "mma.sync.aligned.m16n8k16.row.col.f32.bf16.bf16.f32 "
        "{%0,%1,%2,%3}, {%4,%5,%6,%7}, {%8,%9}, {%0,%1,%2,%3};"
        : "+f"(d[0]), "+f"(d[1]), "+f"(d[2]), "+f"(d[3])
        : "r"(a[0]), "r"(a[1]), "r"(a[2]), "r"(a[3]), "r"(b[0]), "r"(b[1]));
}
__device__ __forceinline__ void cp16(uint32_t dst, const void* src) {
    asm volatile("cp.async.cg.shared.global [%0], [%1], 16;" :: "r"(dst), "l"(src));
}
#define CP_COMMIT() asm volatile("cp.async.commit_group;" ::: "memory")
#define CP_WAIT(n)  asm volatile("cp.async.wait_group %0;" :: "n"(n) : "memory")

#define TROW 136
#define RB   (TROW * 2)            // 272
#define AT128 (128 * RB)           // 34816
#define SM6   (6 * AT128)          // 208896

// fp32 -> hi/lo bf16 split (128 rows) into padded smem tiles
__device__ __forceinline__ void load_a_split(char* hi, char* lo,
        const float* __restrict__ src, int row0, int tid) {
#pragma unroll
    for (int i = 0; i < 16; i++) {
        int f = tid + 256 * i;
        int r = f >> 5, c4 = (f & 31) * 4;
        int gr = row0 + r;
        float4 v = make_float4(0.f, 0.f, 0.f, 0.f);
        if (gr < NN) v = *(const float4*)(src + (size_t)gr * DD + c4);
        __nv_bfloat16 h0 = __float2bfloat16(v.x), h1 = __float2bfloat16(v.y);
        __nv_bfloat16 h2 = __float2bfloat16(v.z), h3 = __float2bfloat16(v.w);
        __nv_bfloat16 l0 = __float2bfloat16(v.x - __bfloat162float(h0));
        __nv_bfloat16 l1 = __float2bfloat16(v.y - __bfloat162float(h1));
        __nv_bfloat16 l2 = __float2bfloat16(v.z - __bfloat162float(h2));
        __nv_bfloat16 l3 = __float2bfloat16(v.w - __bfloat162float(h3));
        __nv_bfloat162 hp0 = {h0, h1}, hp1 = {h2, h3};
        __nv_bfloat162 lp0 = {l0, l1}, lp1 = {l2, l3};
        uint32_t off = r * RB + c4 * 2;
        *(uint2*)(hi + off) = make_uint2(*(uint32_t*)&hp0, *(uint32_t*)&hp1);
        *(uint2*)(lo + off) = make_uint2(*(uint32_t*)&lp0, *(uint32_t*)&lp1);
    }
}
// async copy of one 128x128 bf16 tile-pair (hi+lo)
__device__ __forceinline__ void load_b_async(char* bh, char* bl,
        const __nv_bfloat16* __restrict__ Bh, const __nv_bfloat16* __restrict__ Bl, int tid) {
    uint32_t uh = smem_u32(bh), ul = smem_u32(bl);
#pragma unroll
    for (int i = 0; i < 8; i++) {
        int f = tid + 256 * i;
        int r = f >> 4, c8 = (f & 15) * 8;
        uint32_t off = r * RB + c8 * 2;
        cp16(uh + off, Bh + r * DD + c8);
        cp16(ul + off, Bl + r * DD + c8);
    }
}

// 3-term split K=128 accumulate into acc[2][8][4] (proven round-4 inner loop)
__device__ __forceinline__ void mma_accum_3term(float acc[2][8][4],
        uint32_t uAH, uint32_t uAL, uint32_t uBH, uint32_t uBL,
        uint32_t aoff, uint32_t boff) {
#pragma unroll
    for (int t = 0; t < 3; t++) {
        uint32_t ua = (t < 2) ? uAH : uAL;
        uint32_t ub = (t == 1) ? uBL : uBH;
#pragma unroll
        for (int k = 0; k < 8; k++) {
            uint32_t kb = k * 32;
            uint32_t afr[2][4], bfr[4][4];
            ldsm_x4(afr[0], ua + aoff + kb);
            ldsm_x4(afr[1], ua + aoff + kb + 16 * RB);
#pragma unroll
            for (int ni = 0; ni < 4; ni++)
                ldsm_x4(bfr[ni], ub + boff + kb + ni * 16 * RB);
#pragma unroll
            for (int mi = 0; mi < 2; mi++)
#pragma unroll
                for (int ni = 0; ni < 4; ni++) {
                    mma16816(acc[mi][ni * 2 + 0], afr[mi], &bfr[ni][0]);
                    mma16816(acc[mi][ni * 2 + 1], afr[mi], &bfr[ni][2]);
                }
        }
    }
}
__device__ __forceinline__ void zero_acc(float acc[2][8][4]) {
#pragma unroll
    for (int mi = 0; mi < 2; mi++)
#pragma unroll
        for (int n8 = 0; n8 < 8; n8++)
#pragma unroll
            for (int j = 0; j < 4; j++) acc[mi][n8][j] = 0.f;
}

// ---------------- transform: 2 types per block, grid (391, 2) -----------
__global__ __launch_bounds__(256, 1) void transform2(const float* __restrict__ bias) {
    extern __shared__ char smem[];
    char* sAH  = smem;
    char* sAL  = smem + AT128;
    char* sB0H = smem + 2 * AT128;
    char* sB0L = smem + 3 * AT128;
    char* sB1H = smem + 4 * AT128;
    char* sB1L = smem + 5 * AT128;
    const int tid = threadIdx.x, wid = tid >> 5, lane = tid & 31;
    const int wm = wid & 3, wn = wid >> 2;
    const int row0 = blockIdx.x * 128;
    const int t0 = blockIdx.y * 2;

    load_b_async(sB0H, sB0L, g_Wt_hi + t0 * 16384, g_Wt_lo + t0 * 16384, tid);
    CP_COMMIT();
    load_b_async(sB1H, sB1L, g_Wt_hi + (t0 + 1) * 16384, g_Wt_lo + (t0 + 1) * 16384, tid);
    CP_COMMIT();
    load_a_split(sAH, sAL, g_h, row0, tid);
    CP_WAIT(1);                       // B0 landed
    __syncthreads();

    const uint32_t aoff = (uint32_t)((wm * 32 + (lane & 15)) * RB + (lane >> 4) * 16);
    const uint32_t boff = (uint32_t)((wn * 64 + ((lane >> 4) & 1) * 8 + (lane & 7)) * RB
                                     + ((lane >> 3) & 1) * 16);
    const uint32_t uAH = smem_u32(sAH), uAL = smem_u32(sAL);

    float acc[2][8][4];
    zero_acc(acc);
    mma_accum_3term(acc, uAH, uAL, smem_u32(sB0H), smem_u32(sB0L), aoff, boff);
#pragma unroll
    for (int mi = 0; mi < 2; mi++) {
        int r0 = row0 + wm * 32 + mi * 16 + (lane >> 2);
#pragma unroll
        for (int n8 = 0; n8 < 8; n8++) {
            int col = wn * 64 + n8 * 8 + (lane & 3) * 2;
            float b0 = bias[t0 * 128 + col], b1 = bias[t0 * 128 + col + 1];
            if (r0 < NN)
                *(float2*)(g_t + (size_t)r0 * 512 + t0 * 128 + col) =
                    make_float2(acc[mi][n8][0] + b0, acc[mi][n8][1] + b1);
            if (r0 + 8 < NN)
                *(float2*)(g_t + (size_t)(r0 + 8) * 512 + t0 * 128 + col) =
                    make_float2(acc[mi][n8][2] + b0, acc[mi][n8][3] + b1);
        }
    }

    CP_WAIT(0);                       // B1 landed (already long since)
    zero_acc(acc);
    mma_accum_3term(acc, uAH, uAL, smem_u32(sB1H), smem_u32(sB1L), aoff, boff);
    const int t1 = t0 + 1;
#pragma unroll
    for (int mi = 0; mi < 2; mi++) {
        int r0 = row0 + wm * 32 + mi * 16 + (lane >> 2);
#pragma unroll
        for (int n8 = 0; n8 < 8; n8++) {
            int col = wn * 64 + n8 * 8 + (lane & 3) * 2;
            float b0 = bias[t1 * 128 + col], b1 = bias[t1 * 128 + col + 1];
            if (r0 < NN)
                *(float2*)(g_t + (size_t)r0 * 512 + t1 * 128 + col) =
                    make_float2(acc[mi][n8][0] + b0, acc[mi][n8][1] + b1);
            if (r0 + 8 < NN)
                *(float2*)(g_t + (size_t)(r0 + 8) * 512 + t1 * 128 + col) =
                    make_float2(acc[mi][n8][2] + b0, acc[mi][n8][3] + b1);
        }
    }
}

// ---------------- gates: grid (391, 2) ----------------------------------
// y=0: rs = a@ih_r + h@hh_r ; in = a@ih_n
// y=1: zs = a@ih_z + h@hh_z ; hn = h@hh_n
__global__ __launch_bounds__(256, 1) void gates2() {
    extern __shared__ char smem[];
    char* sAaH = smem;
    char* sAaL = smem + AT128;
    char* sAhH = smem + 2 * AT128;
    char* sAhL = smem + 3 * AT128;
    char* sBH  = smem + 4 * AT128;
    char* sBL  = smem + 5 * AT128;
    const int tid = threadIdx.x, wid = tid >> 5, lane = tid & 31;
    const int wm = wid & 3, wn = wid >> 2;
    const int row0 = blockIdx.x * 128;
    const int y = blockIdx.y;        // 0: r-chunk, 1: z-chunk
    const int ck = y;                // wih/whh chunk for pass 0/1 (r or z)

    // pass-0 B: ih_ck
    load_b_async(sBH, sBL, g_Bih_hi + ck * 16384, g_Bih_lo + ck * 16384, tid);
    CP_COMMIT();
    load_a_split(sAaH, sAaL, g_a, row0, tid);
    load_a_split(sAhH, sAhL, g_h, row0, tid);
    CP_WAIT(0);
    __syncthreads();

    const uint32_t aoff = (uint32_t)((wm * 32 + (lane & 15)) * RB + (lane >> 4) * 16);
    const uint32_t boff = (uint32_t)((wn * 64 + ((lane >> 4) & 1) * 8 + (lane & 7)) * RB
                                     + ((lane >> 3) & 1) * 16);
    const uint32_t uAaH = smem_u32(sAaH), uAaL = smem_u32(sAaL);
    const uint32_t uAhH = smem_u32(sAhH), uAhL = smem_u32(sAhL);
    const uint32_t uBH = smem_u32(sBH), uBL = smem_u32(sBL);

    float acc[2][8][4];
    zero_acc(acc);
    // pass 0: a @ ih_ck
    mma_accum_3term(acc, uAaH, uAaL, uBH, uBL, aoff, boff);
    // pass 1: + h @ hh_ck
    __syncthreads();
    load_b_async(sBH, sBL, g_Bhh_hi + ck * 16384, g_Bhh_lo + ck * 16384, tid);
    CP_COMMIT(); CP_WAIT(0);
    __syncthreads();
    mma_accum_3term(acc, uAhH, uAhL, uBH, uBL, aoff, boff);
    {
        float* C = (y == 0) ? g_rs : g_zs;
#pragma unroll
        for (int mi = 0; mi < 2; mi++) {
            int r0 = row0 + wm * 32 + mi * 16 + (lane >> 2);
#pragma unroll
            for (int n8 = 0; n8 < 8; n8++) {
                int col = wn * 64 + n8 * 8 + (lane & 3) * 2;
                if (r0 < NN)
                    *(float2*)(C + (size_t)r0 * DD + col) =
                        make_float2(acc[mi][n8][0], acc[mi][n8][1]);
                if (r0 + 8 < NN)
                    *(float2*)(C + (size_t)(r0 + 8) * DD + col) =
                        make_float2(acc[mi][n8][2], acc[mi][n8][3]);
            }
        }
    }
    // pass 2: n-chunk. y=0: in = a@ih_n ; y=1: hn = h@hh_n
    __syncthreads();
    if (y == 0) load_b_async(sBH, sBL, g_Bih_hi + 2 * 16384, g_Bih_lo + 2 * 16384, tid);
    else        load_b_async(sBH, sBL, g_Bhh_hi + 2 * 16384, g_Bhh_lo + 2 * 16384, tid);
    CP_COMMIT(); CP_WAIT(0);
    __syncthreads();
    zero_acc(acc);
    if (y == 0) mma_accum_3term(acc, uAaH, uAaL, uBH, uBL, aoff, boff);
    else        mma_accum_3term(acc, uAhH, uAhL, uBH, uBL, aoff, boff);
    {
        float* C = (y == 0) ? g_in : g_hn;
#pragma unroll
        for (int mi = 0; mi < 2; mi++) {
            int r0 = row0 + wm * 32 + mi * 16 + (lane >> 2);
#pragma unroll
            for (int n8 = 0; n8 < 8; n8++) {
                int col = wn * 64 + n8 * 8 + (lane & 3) * 2;
                if (r0 < NN)
                    *(float2*)(C + (size_t)r0 * DD + col) =
                        make_float2(acc[mi][n8][0], acc[mi][n8][1]);
                if (r0 + 8 < NN)
                    *(float2*)(C + (size_t)(r0 + 8) * DD + col) =
                        make_float2(acc[mi][n8][2], acc[mi][n8][3]);
            }
        }
    }
}

// ---------------- weight prep ----------------
__global__ void prep_wmsg(const float* __restrict__ Wmsg) {
    int idx = blockIdx.x * blockDim.x + threadIdx.x;
    if (idx >= TT * DD * DD) return;
    int t = idx >> 14, rem = idx & 16383, e = rem >> 7, d = rem & 127;
    float w = Wmsg[t * 16384 + d * 128 + e];
    __nv_bfloat16 hi = __float2bfloat16(w);
    g_Wt_hi[idx] = hi;
    g_Wt_lo[idx] = __float2bfloat16(w - __bfloat162float(hi));
}
__global__ void prep_gates(const float* __restrict__ wih, const float* __restrict__ whh) {
    int idx = blockIdx.x * blockDim.x + threadIdx.x;
    if (idx >= 3 * DD * DD) return;
    int c = idx >> 7, k = idx & 127;
    float wi = wih[k * 384 + c];
    float wh = whh[k * 384 + c];
    __nv_bfloat16 hi = __float2bfloat16(wi);
    g_Bih_hi[idx] = hi;
    g_Bih_lo[idx] = __float2bfloat16(wi - __bfloat162float(hi));
    __nv_bfloat16 hh = __float2bfloat16(wh);
    g_Bhh_hi[idx] = hh;
    g_Bhh_lo[idx] = __float2bfloat16(wh - __bfloat162float(hh));
}

// ---------------- init ----------------
__global__ void init_kernel(const float* __restrict__ features) {
    int idx = blockIdx.x * blockDim.x + threadIdx.x;
    if (idx >= NN * DD) return;
    int n = idx >> 7, j = idx & 127;
    float v = (j < DIN) ? features[n * DIN + j] : 0.f;
    g_h1[idx] = v;
    g_h [idx] = v;
}

// ---------------- CSR build ----------------
__global__ void zero_cnt_kernel() {
    int i = blockIdx.x * blockDim.x + threadIdx.x;
    if (i < NN) g_cnt[i] = 0;
}
__global__ void count_kernel(const int* __restrict__ dst) {
    int e = blockIdx.x * blockDim.x + threadIdx.x;
    if (e >= EE) return;
    g_eoff[e] = atomicAdd(&g_cnt[dst[e]], 1);
}
__global__ void scan_a_kernel() {
    __shared__ int s[256];
    int b = blockIdx.x, t = threadIdx.x;
    int n = b * 256 + t;
    int v = (n < NN) ? g_cnt[n] : 0;
    s[t] = v;
    __syncthreads();
    for (int d = 1; d < 256; d <<= 1) {
        int x = (t >= d) ? s[t - d] : 0;
        __syncthreads();
        s[t] += x;
        __syncthreads();
    }
    if (n < NN) g_scan[n] = s[t] - v;
    if (t == 255) g_part[b] = s[255];
}
__global__ void scan_b_kernel() {
    __shared__ int s[256];
    int t = threadIdx.x;
    int v = (t < NB1) ? g_part[t] : 0;
    s[t] = v;
    __syncthreads();
    for (int d = 1; d < 256; d <<= 1) {
        int x = (t >= d) ? s[t - d] : 0;
        __syncthreads();
        s[t] += x;
        __syncthreads();
    }
    g_part2[t] = s[t] - v;
}
__global__ void scan_c_kernel() {
    int n = blockIdx.x * blockDim.x + threadIdx.x;
    if (n < NN) g_off[n] = g_scan[n] + g_part2[n >> 8];
    if (n == 0) g_off[NN] = EE;
}
__global__ void fill_kernel(const int* __restrict__ src, const int* __restrict__ dst,
                            const int* __restrict__ et) {
    int e = blockIdx.x * blockDim.x + threadIdx.x;
    if (e >= EE) return;
    int pos = g_off[dst[e]] + g_eoff[e];
    g_gsrc[pos] = src[e] * 512 + et[e] * 128;
}

// ---------------- gather ----------------
__global__ __launch_bounds__(256) void gather_kernel() {
    int w = blockIdx.x * 8 + (threadIdx.x >> 5);
    if (w >= NN) return;
    int lane = threadIdx.x & 31;
    int b0 = g_off[w], b1 = g_off[w + 1];
    float4 acc = make_float4(0.f, 0.f, 0.f, 0.f);
    for (int i = b0; i < b1; i++) {
        int so = g_gsrc[i];
        float4 v = *(const float4*)&g_t[so + lane * 4];
        acc.x += v.x; acc.y += v.y; acc.z += v.z; acc.w += v.w;
    }
    *(float4*)&g_a[w * DD + lane * 4] = acc;
}

// ---------------- GRU pointwise ----------------
__global__ void gru_kernel(const float* __restrict__ bih, const float* __restrict__ bhh) {
    int idx = blockIdx.x * blockDim.x + threadIdx.x;
    if (idx >= NN * 32) return;
    int n = idx >> 5, q = idx & 31;
    int col = q * 4;
    size_t o = (size_t)n * DD + col;
    float4 rs = *(const float4*)&g_rs[o];
    float4 zs = *(const float4*)&g_zs[o];
    float4 iv = *(const float4*)&g_in[o];
    float4 hv = *(const float4*)&g_hn[o];
    float4 h  = *(const float4*)&g_h [o];
    float4 br  = *(const float4*)&bih[col];
    float4 br2 = *(const float4*)&bhh[col];
    float4 bz  = *(const float4*)&bih[128 + col];
    float4 bz2 = *(const float4*)&bhh[128 + col];
    float4 bn  = *(const float4*)&bih[256 + col];
    float4 bn2 = *(const float4*)&bhh[256 + col];
    float4 out;
    {
        float r = 1.f / (1.f + expf(-(rs.x + br.x + br2.x)));
        float z = 1.f / (1.f + expf(-(zs.x + bz.x + bz2.x)));
        float ng = tanhf(iv.x + bn.x + r * (hv.x + bn2.x));
        out.x = (1.f - z) * ng + z * h.x;
    }
    {
        float r = 1.f / (1.f + expf(-(rs.y + br.y + br2.y)));
        float z = 1.f / (1.f + expf(-(zs.y + bz.y + bz2.y)));
        float ng = tanhf(iv.y + bn.y + r * (hv.y + bn2.y));
        out.y = (1.f - z) * ng + z * h.y;
    }
    {
        float r = 1.f / (1.f + expf(-(rs.z + br.z + br2.z)));
        float z = 1.f / (1.f + expf(-(zs.z + bz.z + bz2.z)));
        float ng = tanhf(iv.z + bn.z + r * (hv.z + bn2.z));
        out.z = (1.f - z) * ng + z * h.z;
    }
    {
        float r = 1.f / (1.f + expf(-(rs.w + br.w + br2.w)));
        float z = 1.f / (1.f + expf(-(zs.w + bz.w + bz2.w)));
        float ng = tanhf(iv.w + bn.w + r * (hv.w + bn2.w));
        out.w = (1.f - z) * ng + z * h.w;
    }
    *(float4*)&g_h[o] = out;
}

// ---------------- pooling + classifier ----------------
__global__ void zero_feats_kernel() {
    int i = blockIdx.x * blockDim.x + threadIdx.x;
    if (i < BG * DD) g_feats[i] = 0.f;
}
__global__ void pool_kernel(const int* __restrict__ n2g) {
    int n0 = blockIdx.x * 64;
    int j  = threadIdx.x;
    if (n0 >= NN) return;
    float acc = 0.f;
    int cur = n2g[n0];
    for (int i = 0; i < 64; i++) {
        int n = n0 + i;
        if (n >= NN) break;
        int g = n2g[n];
        if (g != cur) {
            atomicAdd(&g_feats[cur * DD + j], acc);
            acc = 0.f; cur = g;
        }
        acc += g_h[n * DD + j] + g_h1[n * DD + j];
    }
    atomicAdd(&g_feats[cur * DD + j], acc);
}
__global__ void cls_kernel(const float* __restrict__ Wc,
                           const float* __restrict__ bc,
                           float* __restrict__ out) {
    int tid = threadIdx.x;
    if (tid >= BG * 2) return;
    int g = tid >> 1, c = tid & 1;
    float s = bc[c];
#pragma unroll 8
    for (int k = 0; k < DD; k++) s += g_feats[g * DD + k] * Wc[k * 2 + c];
    out[g * 2 + c] = s;
}

// ---------------- launch ----------------
extern "C" void kernel_launch(void* const* d_in, const int* in_sizes, int n_in,
                              void* d_out, int out_size) {
    const float* features = (const float*)d_in[0];
    const int*   src      = (const int*)  d_in[1];
    const int*   dst      = (const int*)  d_in[2];
    const int*   etype    = (const int*)  d_in[3];
    const int*   n2g      = (const int*)  d_in[4];
    const float* W_msg    = (const float*)d_in[5];
    const float* b_msg    = (const float*)d_in[6];
    const float* w_ih     = (const float*)d_in[7];
    const float* b_ih     = (const float*)d_in[8];
    const float* w_hh     = (const float*)d_in[9];
    const float* b_hh     = (const float*)d_in[10];
    const float* W_cls    = (const float*)d_in[11];
    const float* b_cls    = (const float*)d_in[12];
    float* out = (float*)d_out;

    static int smem_set = 0;
    if (!smem_set) {
        cudaFuncSetAttribute(transform2,
                             cudaFuncAttributeMaxDynamicSharedMemorySize, SM6);
        cudaFuncSetAttribute(gates2,
                             cudaFuncAttributeMaxDynamicSharedMemorySize, SM6);
        smem_set = 1;
    }

    // prologue
    prep_wmsg<<<(TT * DD * DD + 255) / 256, 256>>>(W_msg);
    prep_gates<<<(3 * DD * DD + 255) / 256, 256>>>(w_ih, w_hh);
    init_kernel<<<(NN * DD + 255) / 256, 256>>>(features);
    zero_cnt_kernel<<<(NN + 255) / 256, 256>>>();
    count_kernel<<<(EE + 255) / 256, 256>>>(dst);
    scan_a_kernel<<<NB1, 256>>>();
    scan_b_kernel<<<1, 256>>>();
    scan_c_kernel<<<(NN + 255) / 256, 256>>>();
    fill_kernel<<<(EE + 255) / 256, 256>>>(src, dst, etype);

    for (int s = 0; s < NSTEPS; s++) {
        transform2<<<dim3(RTILES, 2), 256, SM6>>>(b_msg);
        gather_kernel<<<(NN + 7) / 8, 256>>>();
        gates2<<<dim3(RTILES, 2), 256, SM6>>>();
        gru_kernel<<<(NN * 32 + 255) / 256, 256>>>(b_ih, b_hh);
    }

    zero_feats_kernel<<<(BG * DD + 255) / 256, 256>>>();
    pool_kernel<<<(NN + 63) / 64, 128>>>(n2g);
    cls_kernel<<<1, 128>>>(W_cls, b_cls, out);
}